// round 17
// baseline (speedup 1.0000x reference)
#include <cuda_runtime.h>

#define N_NODES 50000
#define N_EDGES 200000
#define F_IN 100
#define HID 1024

#define NB_FOLD  (F_IN + 1)                        // 101 fold blocks
#define NB_DEG   ((N_NODES + 255) / 256)           // 196 per-node blocks
#define NB_E4    ((N_EDGES / 4 + 255) / 256)       // 196 deg blocks (4 edges/thr)
#define NB_NODE2 ((N_NODES / 2 * 32 + 255) / 256)  // 3125 dot blocks (2 nodes/warp)
#define NB_E2    ((N_EDGES / 2 + 255) / 256)       // 391 scatter blocks (2/thr)

// Scratch (no device allocation allowed).
// g_deg starts 0 (zero-init), reset to 0 by K3 each run (read-then-zero).
// g_acc starts 0 (zero-init), re-zeroed by K1's trailing blocks each run.
__device__ float g_w[F_IN];
__device__ float g_c;
__device__ float g_deg[N_NODES];
__device__ float g_dinv[N_NODES];
__device__ float g_s[N_NODES];
__device__ float g_p[N_NODES];
__device__ float g_acc[N_NODES];   // sum of p[src] per dst (dinv factored out)

// Per-block edge-dtype detect (input-only): int64-LE values < 50000 have
// all-zero odd 32-bit words; 128 random int32 endpoints all zero: prob ~ 0.
__device__ __forceinline__ bool detect_is64_inline(const int* __restrict__ ebuf) {
    __shared__ int nz;
    if (threadIdx.x == 0) nz = 0;
    __syncthreads();
    if (threadIdx.x < 128 && ebuf[2 * threadIdx.x + 1] != 0) nz = 1;
    __syncthreads();
    return nz == 0;
}

// ---------------------------------------------------------------------------
// K1: fold w = W1 @ W_head (and c) || zero g_acc (trailing 196 blocks).
// ---------------------------------------------------------------------------
__global__ void __launch_bounds__(256)
setup_kernel(const float* __restrict__ W1,
             const float* __restrict__ b1,
             const float* __restrict__ Wh,
             const float* __restrict__ bh) {
    int blk = blockIdx.x;
    int t = threadIdx.x;

    if (blk < NB_FOLD) {
        __shared__ float red[256];
        float acc = 0.f;
        if (blk < F_IN) {
            const float* row = W1 + (long long)blk * HID;
            for (int k = t; k < HID; k += 256) acc += row[k] * Wh[k];
        } else {
            for (int k = t; k < HID; k += 256) acc += b1[k] * Wh[k];
        }
        red[t] = acc;
        __syncthreads();
        for (int s = 128; s > 0; s >>= 1) {
            if (t < s) red[t] += red[t + s];
            __syncthreads();
        }
        if (t == 0) {
            if (blk < F_IN) g_w[blk] = red[0];
            else            g_c     = red[0] + bh[0];
        }
        return;
    }
    int i = (blk - NB_FOLD) * 256 + t;
    if (i < N_NODES) g_acc[i] = 0.0f;          // zero msg accumulator per replay
}

// ---------------------------------------------------------------------------
// K2 (PDL): deg blocks first (196 blocks, 4 edges/thread, int4 loads; no
// dependency sync — K1 never touches g_deg). Dot blocks after: 2 nodes/warp,
// 8 independent scalar prologue loads.
// ---------------------------------------------------------------------------
__global__ void __launch_bounds__(256)
dot_and_deg_kernel(const float* __restrict__ x,
                   const int* __restrict__ ebuf) {
    int blk = blockIdx.x;
    int t = threadIdx.x;

    if (blk < NB_E4) {
        bool is64 = detect_is64_inline(ebuf);
        int e = (blk * 256 + t) * 4;
        if (e < N_EDGES) {   // N_EDGES % 4 == 0: no partial batches
            int d0, d1, d2, d3;
            if (is64) {
                long long base = ((long long)N_EDGES + e) >> 1;  // int4 units
                int4 v0 = ((const int4*)ebuf)[base];
                int4 v1 = ((const int4*)ebuf)[base + 1];
                d0 = v0.x; d1 = v0.z; d2 = v1.x; d3 = v1.z;
            } else {
                int4 v = ((const int4*)ebuf)[((long long)N_EDGES + e) >> 2];
                d0 = v.x; d1 = v.y; d2 = v.z; d3 = v.w;
            }
            if ((unsigned)d0 < N_NODES) atomicAdd(&g_deg[d0], 1.0f);
            if ((unsigned)d1 < N_NODES) atomicAdd(&g_deg[d1], 1.0f);
            if ((unsigned)d2 < N_NODES) atomicAdd(&g_deg[d2], 1.0f);
            if ((unsigned)d3 < N_NODES) atomicAdd(&g_deg[d3], 1.0f);
        }
        return;
    }

    int warp = ((blk - NB_E4) * 256 + t) >> 5;
    int lane = t & 31;
    int n0 = warp * 2;
    int n1 = n0 + 1;

    // prologue: 8 independent scalar loads (two x rows), input only
    float a0 = 0.f, a1 = 0.f, a2 = 0.f, a3 = 0.f;
    float b0 = 0.f, b1v = 0.f, b2 = 0.f, b3 = 0.f;
    if (n1 < N_NODES) {   // N_NODES even: n0 valid iff n1 valid
        const float* xa = x + (long long)n0 * F_IN;
        const float* xb = x + (long long)n1 * F_IN;
        a0 = xa[lane];
        b0 = xb[lane];
        a1 = xa[lane + 32];
        b1v = xb[lane + 32];
        a2 = xa[lane + 64];
        b2 = xb[lane + 64];
        if (lane < 4) { a3 = xa[lane + 96]; b3 = xb[lane + 96]; }
    }

    cudaGridDependencySynchronize();           // g_w ready

    __shared__ float sw[F_IN];
    for (int i = t; i < F_IN; i += 256) sw[i] = g_w[i];
    __syncthreads();
    if (n1 >= N_NODES) return;

    float w0 = sw[lane], w1 = sw[lane + 32], w2 = sw[lane + 64];
    float w3 = (lane < 4) ? sw[lane + 96] : 0.f;

    float accA = a0 * w0 + a1 * w1 + a2 * w2 + a3 * w3;
    float accB = b0 * w0 + b1v * w1 + b2 * w2 + b3 * w3;

    #pragma unroll
    for (int o = 16; o > 0; o >>= 1) {
        accA += __shfl_down_sync(0xffffffffu, accA, o);
        accB += __shfl_down_sync(0xffffffffu, accB, o);
    }

    if (lane == 0) {
        g_s[n0] = accA;
        g_s[n1] = accB;
    }
}

// ---------------------------------------------------------------------------
// K3 (PDL): per-node finalize (coalesced): dinv, p; resets g_deg to 0 for
// the next graph replay (read-then-zero). Does NOT touch out.
// ---------------------------------------------------------------------------
__global__ void __launch_bounds__(256)
node_finalize() {
    cudaGridDependencySynchronize();           // deg atomics + s complete
    int n = blockIdx.x * blockDim.x + threadIdx.x;
    if (n < N_NODES) {
        float deg = g_deg[n] + 1.0f;           // +1 self loop (zero-based counter)
        g_deg[n] = 0.0f;                       // restore for next replay
        float d = rsqrtf(deg);
        g_dinv[n] = d;
        g_p[n]    = g_s[n] * d;
    }
}

// ---------------------------------------------------------------------------
// K4 (PDL): edge scatter, 2 edges/thread: acc[dst] += p[src].
// dinv factored out -> only ONE post-sync gather per edge.
// ---------------------------------------------------------------------------
__global__ void __launch_bounds__(256)
edge_scatter(const int* __restrict__ ebuf) {
    bool is64 = detect_is64_inline(ebuf);
    int e = (blockIdx.x * 256 + threadIdx.x) * 2;

    int s0 = -1, s1 = -1, d0 = -1, d1 = -1;
    if (e < N_EDGES) {   // N_EDGES even: no partial pairs
        if (is64) {
            int4 vs = ((const int4*)ebuf)[e >> 1];
            int4 vd = ((const int4*)ebuf)[((long long)N_EDGES + e) >> 1];
            s0 = vs.x; s1 = vs.z; d0 = vd.x; d1 = vd.z;
        } else {
            int2 vs = ((const int2*)ebuf)[e >> 1];
            int2 vd = ((const int2*)ebuf)[((long long)N_EDGES + e) >> 1];
            s0 = vs.x; s1 = vs.y; d0 = vd.x; d1 = vd.y;
        }
    }
    bool v0 = (unsigned)s0 < N_NODES && (unsigned)d0 < N_NODES;
    bool v1 = (unsigned)s1 < N_NODES && (unsigned)d1 < N_NODES;

    cudaGridDependencySynchronize();           // p complete

    float p0 = v0 ? g_p[s0] : 0.f;
    float p1 = v1 ? g_p[s1] : 0.f;

    if (v0) atomicAdd(&g_acc[d0], p0);
    if (v1) atomicAdd(&g_acc[d1], p1);
}

// ---------------------------------------------------------------------------
// K5 (PDL): single coalesced out write: out[n] = c + dinv*(p + acc)
// (self-loop msg s*dinv^2 = p*dinv, plus normalized neighbor sum)
// ---------------------------------------------------------------------------
__global__ void __launch_bounds__(256)
out_write(float* __restrict__ out) {
    cudaGridDependencySynchronize();           // acc atomics complete
    int n = blockIdx.x * blockDim.x + threadIdx.x;
    if (n < N_NODES)
        out[n] = fmaf(g_dinv[n], g_p[n] + g_acc[n], g_c);
}

// ---------------------------------------------------------------------------
// Host: PDL launches (programmatic stream serialization)
// ---------------------------------------------------------------------------
template <typename... Args>
static inline void launch_pdl(void (*kern)(Args...), dim3 grid, Args... args) {
    cudaLaunchConfig_t cfg = {};
    cudaLaunchAttribute attr[1];
    attr[0].id = cudaLaunchAttributeProgrammaticStreamSerialization;
    attr[0].val.programmaticStreamSerializationAllowed = 1;
    cfg.gridDim = grid;
    cfg.blockDim = dim3(256, 1, 1);
    cfg.dynamicSmemBytes = 0;
    cfg.stream = 0;
    cfg.attrs = attr;
    cfg.numAttrs = 1;
    cudaLaunchKernelEx(&cfg, kern, args...);
}

extern "C" void kernel_launch(void* const* d_in, const int* in_sizes, int n_in,
                              void* d_out, int out_size) {
    const float* state = (const float*)d_in[0];  // [N, 100, 1] f32
    const int*   ebuf  = (const int*)  d_in[1];  // [2, 200000] int32/int64 layout
    const float* W1    = (const float*)d_in[2];  // [100, 1024]
    const float* b1    = (const float*)d_in[3];  // [1024]
    const float* Wh    = (const float*)d_in[4];  // [1024, 1]
    const float* bh    = (const float*)d_in[5];  // [1]
    float* out = (float*)d_out;                  // [N, 1]

    setup_kernel<<<NB_FOLD + NB_DEG, 256>>>(W1, b1, Wh, bh);
    launch_pdl(dot_and_deg_kernel, dim3(NB_E4 + NB_NODE2, 1, 1), state, ebuf);
    launch_pdl(node_finalize, dim3(NB_DEG, 1, 1));
    launch_pdl(edge_scatter, dim3(NB_E2, 1, 1), (const int*)ebuf);
    launch_pdl(out_write, dim3(NB_DEG, 1, 1), (float*)out);
}